// round 11
// baseline (speedup 1.0000x reference)
#include <cuda_runtime.h>
#include <cstdint>

// ---------------------------------------------------------------- constants
#define B_   4
#define S_   2048
#define D_   512
#define H_   8
#define HD_  64
#define L_   128
#define BS_  (B_ * S_)

#define OP_NONE    0
#define OP_RELU    1
#define OP_SIGMOID 2
#define OP_MUL     3

// ---------------------------------------------------------------- scratch
__device__ float g_latent[BS_ * L_];
__device__ float g_modq[BS_ * D_];
__device__ float g_modk[BS_ * D_];
__device__ float g_q[BS_ * D_];
__device__ float g_k[BS_ * D_];
__device__ float g_v[BS_ * D_];
__device__ float g_ao[BS_ * D_];
__device__ float g_vt[B_ * H_ * HD_ * S_];      // [bh][hd][s]
__device__ float g_stats[B_ * H_ * S_];         // per attn row: 1/sum
__device__ float g_WgT[L_ * D_];
__device__ float g_WmqT[D_ * L_];
__device__ float g_WmkT[D_ * L_];
__device__ float g_WqT[D_ * D_];
__device__ float g_WkT[D_ * D_];
__device__ float g_WvT[D_ * D_];
__device__ float g_WoT[D_ * D_];

// ---------------------------------------------------------------- helpers
__device__ __forceinline__ uint32_t tf32r(float x) {
    float r;
    asm("cvt.rna.tf32.f32 %0, %1;" : "=f"(r) : "f"(x));
    return __float_as_uint(r);
}
__device__ __forceinline__ float tf32f(float x) {
    float r;
    asm("cvt.rna.tf32.f32 %0, %1;" : "=f"(r) : "f"(x));
    return r;
}
__device__ __forceinline__ uint32_t smem_u32(const void* p) {
    uint32_t a;
    asm("{ .reg .u64 t; cvta.to.shared.u64 t, %1; cvt.u32.u64 %0, t; }"
        : "=r"(a) : "l"(p));
    return a;
}
__device__ __forceinline__ void cp16(uint32_t saddr, const void* gaddr) {
    asm volatile("cp.async.cg.shared.global [%0], [%1], 16;"
                 :: "r"(saddr), "l"(gaddr));
}
#define CP_COMMIT() asm volatile("cp.async.commit_group;")
#define CP_WAIT1()  asm volatile("cp.async.wait_group 1;" ::: "memory")
#define CP_WAIT0()  asm volatile("cp.async.wait_group 0;" ::: "memory")

__device__ __forceinline__ void mma_tf32_16x8x8(
    float& c0, float& c1, float& c2, float& c3,
    uint32_t a0, uint32_t a1, uint32_t a2, uint32_t a3,
    uint32_t b0, uint32_t b1)
{
    asm volatile(
        "mma.sync.aligned.m16n8k8.row.col.f32.tf32.tf32.f32 "
        "{%0,%1,%2,%3}, {%4,%5,%6,%7}, {%8,%9}, {%0,%1,%2,%3};"
        : "+f"(c0), "+f"(c1), "+f"(c2), "+f"(c3)
        : "r"(a0), "r"(a1), "r"(a2), "r"(a3), "r"(b0), "r"(b1));
}

// ---------------------------------------------------------------- tc GEMM
// D[M,N] = op(A[M,K] @ B[N,K]^T + bias). B pre-rounded to tf32 in gmem.
// 128 threads = 4 warps in 2(m) x 2(n); warp tile 64x64 (FM=4, NF=8).
// LDS redundancy per chunk: 2x A + 2x B = 64 KB (was 96 KB with 8 warps).
// B staged via cp.async directly into chunked fragment layout:
//   word = ((fn*4+ks)*2 + half)*32 + g*4 + t   (16B chunks, conflict-free)
struct GemmJob { const float *A, *Bm, *bias, *aux; float *C; };
struct GemmJobs { GemmJob j[2]; };

template<int OP, bool RND>
__global__ void __launch_bounds__(128, 2)
tc_gemm(GemmJobs jobs, int lda, int ldb, int ldc, int M, int N, int K)
{
    const GemmJob J = jobs.j[blockIdx.z];
    const float* __restrict__ A    = J.A;
    const float* __restrict__ Bm   = J.Bm;
    const float* __restrict__ bias = J.bias;
    const float* __restrict__ aux  = J.aux;
    float* __restrict__ C          = J.C;

    extern __shared__ float sm[];
    float* const A0 = sm;                 // 4096 floats
    float* const A1 = A0 + 4096;
    float* const B0 = A1 + 4096;          // 4096 floats
    float* const B1 = B0 + 4096;
    const uint32_t sB0 = smem_u32(B0);
    const uint32_t sB1 = smem_u32(B1);

    const int tid  = threadIdx.x;
    const int wid  = tid >> 5;
    const int lane = tid & 31;
    const int wm   = wid >> 1;            // 0..1
    const int wn   = wid & 1;             // 0..1
    const int g    = lane >> 2;
    const int t    = lane & 3;

    const int m0 = blockIdx.y * 128;
    const int n0 = blockIdx.x * 128;
    const int NC = K >> 5;

    float acc[4][8][4];
#pragma unroll
    for (int i = 0; i < 4; i++)
#pragma unroll
        for (int j = 0; j < 8; j++)
#pragma unroll
            for (int r = 0; r < 4; r++) acc[i][j][r] = 0.f;

    float4 ar[8];

    auto loadA = [&](int kc) {
        const float* Ag = A + (long long)m0 * lda + kc * 32;
#pragma unroll
        for (int i = 0; i < 8; i++) {
            int idx = tid + i * 128;
            int m = idx >> 3, f4 = idx & 7;
            ar[i] = *(const float4*)(Ag + (long long)m * lda + f4 * 4);
        }
    };
    auto cpB = [&](uint32_t sB, int kc) {
        const float* Bg = Bm + (long long)n0 * ldb + kc * 32;
#pragma unroll
        for (int i = 0; i < 8; i++) {
            int idx = tid + i * 128;
            int n = idx >> 3, c = idx & 7;          // c: 16B chunk (ks,half)
            int fn = n >> 3, gg = n & 7;
            uint32_t dst = sB + (((fn * 4 + (c >> 1)) * 2 + (c & 1)) * 32
                                 + gg * 4) * 4;
            cp16(dst, Bg + (long long)n * ldb + c * 4);
        }
    };
    auto stsA = [&](float* As) {
#pragma unroll
        for (int i = 0; i < 8; i++) {
            int idx = tid + i * 128;
            int m = idx >> 3, f4 = idx & 7;
            int fm = m >> 4, r = m & 15, ks = f4 >> 1, c4h = f4 & 1;
            int base = (fm * 4 + ks) * 128 + (r & 7) * 16 + (r >> 3) + (c4h << 1);
            uint32_t* Au = (uint32_t*)As;
            Au[base +  0] = tf32r(ar[i].x);
            Au[base +  4] = tf32r(ar[i].y);
            Au[base +  8] = tf32r(ar[i].z);
            Au[base + 12] = tf32r(ar[i].w);
        }
    };
    auto compute = [&](const float* As, const float* Bs) {
#pragma unroll
        for (int ks = 0; ks < 4; ks++) {
            uint32_t bf[8][2];
#pragma unroll
            for (int fn = 0; fn < 8; fn++) {
                const int base = ((wn * 8 + fn) * 4 + ks) * 64;
                bf[fn][0] = __float_as_uint(Bs[base + g * 4 + t]);
                bf[fn][1] = __float_as_uint(Bs[base + 32 + g * 4 + t]);
            }
            uint32_t af[4][4];
#pragma unroll
            for (int fm = 0; fm < 4; fm++) {
                const float4 v = *(const float4*)
                    &As[(((wm * 4 + fm) * 4 + ks) * 32 + lane) * 4];
                af[fm][0] = __float_as_uint(v.x);
                af[fm][1] = __float_as_uint(v.y);
                af[fm][2] = __float_as_uint(v.z);
                af[fm][3] = __float_as_uint(v.w);
            }
#pragma unroll
            for (int fm = 0; fm < 4; fm++)
#pragma unroll
                for (int fn = 0; fn < 8; fn++)
                    mma_tf32_16x8x8(acc[fm][fn][0], acc[fm][fn][1],
                                    acc[fm][fn][2], acc[fm][fn][3],
                                    af[fm][0], af[fm][1], af[fm][2], af[fm][3],
                                    bf[fn][0], bf[fn][1]);
        }
    };

    // prologue
    loadA(0);
    cpB(sB0, 0);
    CP_COMMIT();
    stsA(A0);
    CP_WAIT0();
    __syncthreads();

    for (int kc = 0; kc < NC; kc++) {
        const int cur = kc & 1;
        if (kc + 1 < NC) {
            loadA(kc + 1);
            cpB(cur ? sB0 : sB1, kc + 1);
            CP_COMMIT();
        }
        compute(cur ? A1 : A0, cur ? B1 : B0);
        if (kc + 1 < NC) {
            stsA(cur ? A0 : A1);
            CP_WAIT0();
            __syncthreads();
        }
    }

    // epilogue
#pragma unroll
    for (int fm = 0; fm < 4; fm++) {
        const int row = m0 + wm * 64 + fm * 16 + g;
#pragma unroll
        for (int fn = 0; fn < 8; fn++) {
            const int col = n0 + wn * 64 + fn * 8 + t * 2;
#pragma unroll
            for (int half = 0; half < 2; half++) {
                const int rr = row + half * 8;
                float v0 = acc[fm][fn][half * 2 + 0];
                float v1 = acc[fm][fn][half * 2 + 1];
                if (bias) { v0 += bias[col]; v1 += bias[col + 1]; }
                if (OP == OP_RELU) {
                    v0 = fmaxf(v0, 0.f); v1 = fmaxf(v1, 0.f);
                } else if (OP == OP_SIGMOID) {
                    v0 = 1.f / (1.f + __expf(-v0));
                    v1 = 1.f / (1.f + __expf(-v1));
                } else if (OP == OP_MUL) {
                    const float2 m2 = *(const float2*)
                        &aux[(long long)rr * ldc + col];
                    v0 *= m2.x; v1 *= m2.y;
                }
                if (RND) { v0 = tf32f(v0); v1 = tf32f(v1); }
                float2 o; o.x = v0; o.y = v1;
                *(float2*)&C[(long long)rr * ldc + col] = o;
            }
        }
    }
}

// ---------------------------------------------------------------- fused attn
// (unchanged R7/R9 structure: streaming e -> P, row sums, O scaled.)
__global__ void __launch_bounds__(512, 1)
attn_fused(const float* __restrict__ qg, const float* __restrict__ kg,
           const float* __restrict__ vtg, float* __restrict__ P,
           float* __restrict__ ao, float* __restrict__ stats)
{
    extern __shared__ float sm[];
    float* const Ks0  = sm;                   // 128*68
    float* const Ks1  = Ks0 + 128 * 68;
    float* const Vs0  = Ks1 + 128 * 68;       // 64*132
    float* const Vs1  = Vs0 + 64 * 132;
    float* const Es   = Vs1 + 64 * 132;       // 128*132
    float* const ssum = Es + 128 * 132;       // 256
    float* const srv  = ssum + 256;           // 128

    const uint32_t sKs0 = smem_u32(Ks0);
    const uint32_t sKs1 = smem_u32(Ks1);
    const uint32_t sVs0 = smem_u32(Vs0);
    const uint32_t sVs1 = smem_u32(Vs1);

    const int tid  = threadIdx.x;
    const int wid  = tid >> 5;
    const int lane = tid & 31;
    const int wm   = wid >> 1;                // 0..7
    const int wn   = wid & 1;                 // 0..1
    const int g    = lane >> 2;
    const int t    = lane & 3;

    const int qt = blockIdx.x, z = blockIdx.y;
    const int b = z >> 3, h = z & 7;
    const long long offQK = (long long)b * S_ * D_ + (long long)h * HD_;
    const long long offP  = (long long)z * S_ * S_ + (long long)(qt * 128) * S_;
    const float* Vg = vtg + (long long)z * HD_ * S_;
    const float sc = 0.125f;

    const int kr = tid >> 4, kf = tid & 15;
    const int vd = tid >> 5, vf = tid & 31;
    auto issueK = [&](uint32_t sbase, int kt) {
        const float* Kg2 = kg + offQK + (long long)(kt * 128) * D_;
#pragma unroll
        for (int i = 0; i < 4; i++) {
            int r = kr + i * 32;
            cp16(sbase + (r * 68 + kf * 4) * 4, Kg2 + (long long)r * D_ + kf * 4);
        }
    };
    auto issueV = [&](uint32_t sbase, int kt) {
#pragma unroll
        for (int i = 0; i < 4; i++) {
            int d = vd + i * 16;
            cp16(sbase + (d * 132 + vf * 4) * 4,
                 Vg + (long long)d * S_ + kt * 128 + vf * 4);
        }
    };

    {
        const float* Qg = qg + offQK + (long long)(qt * 128) * D_;
#pragma unroll
        for (int i = 0; i < 4; i++) {
            int idx = tid + i * 512;
            int r = idx >> 4, f4 = idx & 15;
            float4 v = *(const float4*)(Qg + (long long)r * D_ + f4 * 4);
            *(float4*)&Es[r * 132 + f4 * 4] = v;
        }
    }
    issueK(sKs0, 0);
    issueV(sVs0, 0);
    CP_COMMIT();
    __syncthreads();

    uint32_t aq[8][4];
    {
        const int r0 = wm * 16 + g;
#pragma unroll
        for (int ks = 0; ks < 8; ks++) {
            aq[ks][0] = __float_as_uint(Es[r0 * 132 + ks * 8 + t]);
            aq[ks][1] = __float_as_uint(Es[(r0 + 8) * 132 + ks * 8 + t]);
            aq[ks][2] = __float_as_uint(Es[r0 * 132 + ks * 8 + t + 4]);
            aq[ks][3] = __float_as_uint(Es[(r0 + 8) * 132 + ks * 8 + t + 4]);
        }
    }

    float acco[4][4];
#pragma unroll
    for (int fn = 0; fn < 4; fn++)
#pragma unroll
        for (int r = 0; r < 4; r++) acco[fn][r] = 0.f;
    float rsum0 = 0.f, rsum1 = 0.f;

    for (int kt = 0; kt < 16; kt++) {
        const int cur = kt & 1;
        __syncthreads();
        if (kt < 15) {
            issueK(cur ? sKs0 : sKs1, kt + 1);
            issueV(cur ? sVs0 : sVs1, kt + 1);
            CP_COMMIT();
            CP_WAIT1();
        } else {
            CP_WAIT0();
        }
        __syncthreads();

        const float* Ksb = cur ? Ks1 : Ks0;
        const float* Vsb = cur ? Vs1 : Vs0;

        float accs[8][4];
#pragma unroll
        for (int fn = 0; fn < 8; fn++)
#pragma unroll
            for (int r = 0; r < 4; r++) accs[fn][r] = 0.f;
#pragma unroll
        for (int ks = 0; ks < 8; ks++) {
#pragma unroll
            for (int fn = 0; fn < 8; fn++) {
                const int n = wn * 64 + fn * 8 + g;
                uint32_t b0 = __float_as_uint(Ksb[n * 68 + ks * 8 + t]);
                uint32_t b1 = __float_as_uint(Ksb[n * 68 + ks * 8 + t + 4]);
                mma_tf32_16x8x8(accs[fn][0], accs[fn][1],
                                accs[fn][2], accs[fn][3],
                                aq[ks][0], aq[ks][1], aq[ks][2], aq[ks][3],
                                b0, b1);
            }
        }

        const int prow0 = wm * 16 + g;
#pragma unroll
        for (int fn = 0; fn < 8; fn++) {
            float2 eA, eB;
            eA.x = __expf(accs[fn][0] * sc);
            eA.y = __expf(accs[fn][1] * sc);
            eB.x = __expf(accs[fn][2] * sc);
            eB.y = __expf(accs[fn][3] * sc);
            rsum0 += eA.x + eA.y;
            rsum1 += eB.x + eB.y;
            const int col = wn * 64 + fn * 8 + t * 2;
            __stcs((float2*)&P[offP + (long long)prow0 * S_ + kt * 128 + col], eA);
            __stcs((float2*)&P[offP + (long long)(prow0 + 8) * S_ + kt * 128 + col], eB);
            float2 rA, rB;
            rA.x = tf32f(eA.x); rA.y = tf32f(eA.y);
            rB.x = tf32f(eB.x); rB.y = tf32f(eB.y);
            *(float2*)&Es[prow0 * 132 + col]       = rA;
            *(float2*)&Es[(prow0 + 8) * 132 + col] = rB;
        }

        asm volatile("bar.sync %0, 64;" :: "r"(1 + wm) : "memory");

#pragma unroll
        for (int ks = 0; ks < 16; ks++) {
            uint32_t a0 = __float_as_uint(Es[prow0 * 132 + ks * 8 + t]);
            uint32_t a1 = __float_as_uint(Es[(prow0 + 8) * 132 + ks * 8 + t]);
            uint32_t a2 = __float_as_uint(Es[prow0 * 132 + ks * 8 + t + 4]);
            uint32_t a3 = __float_as_uint(Es[(prow0 + 8) * 132 + ks * 8 + t + 4]);
#pragma unroll
            for (int fn = 0; fn < 4; fn++) {
                const int n = wn * 32 + fn * 8 + g;
                uint32_t b0 = __float_as_uint(Vsb[n * 132 + ks * 8 + t]);
                uint32_t b1 = __float_as_uint(Vsb[n * 132 + ks * 8 + t + 4]);
                mma_tf32_16x8x8(acco[fn][0], acco[fn][1],
                                acco[fn][2], acco[fn][3],
                                a0, a1, a2, a3, b0, b1);
            }
        }
    }

    rsum0 += __shfl_xor_sync(~0u, rsum0, 1);
    rsum0 += __shfl_xor_sync(~0u, rsum0, 2);
    rsum1 += __shfl_xor_sync(~0u, rsum1, 1);
    rsum1 += __shfl_xor_sync(~0u, rsum1, 2);
    __syncthreads();
    if (t == 0) {
        ssum[(wm * 16 + g) * 2 + wn]     = rsum0;
        ssum[(wm * 16 + g + 8) * 2 + wn] = rsum1;
    }
    __syncthreads();
    if (tid < 128) {
        float rv = 1.f / (ssum[tid * 2] + ssum[tid * 2 + 1]);
        srv[tid] = rv;
        stats[(long long)z * S_ + qt * 128 + tid] = rv;
    }
    __syncthreads();
    const float rv0 = srv[wm * 16 + g];
    const float rv1 = srv[wm * 16 + g + 8];

    const long long offC = (long long)b * S_ * D_ + (long long)h * HD_;
#pragma unroll
    for (int fn = 0; fn < 4; fn++) {
        const int col = wn * 32 + fn * 8 + t * 2;
        const int row = qt * 128 + wm * 16 + g;
        float2 oA, oB;
        oA.x = tf32f(acco[fn][0] * rv0); oA.y = tf32f(acco[fn][1] * rv0);
        oB.x = tf32f(acco[fn][2] * rv1); oB.y = tf32f(acco[fn][3] * rv1);
        *(float2*)&ao[offC + (long long)row * D_ + col] = oA;
        *(float2*)&ao[offC + (long long)(row + 8) * D_ + col] = oB;
    }
}

// ---------------------------------------------------------------- P scale
__global__ void __launch_bounds__(256)
p_scale(float* __restrict__ P, const float* __restrict__ stats)
{
    const long long row = blockIdx.x;
    float* p = P + row * S_;
    const float rv = stats[row];
    const int tid = threadIdx.x;
    float4 v0 = __ldcs((const float4*)(p + tid * 4));
    float4 v1 = __ldcs((const float4*)(p + (tid + 256) * 4));
    v0.x *= rv; v0.y *= rv; v0.z *= rv; v0.w *= rv;
    v1.x *= rv; v1.y *= rv; v1.z *= rv; v1.w *= rv;
    __stcs((float4*)(p + tid * 4), v0);
    __stcs((float4*)(p + (tid + 256) * 4), v1);
}

// ---------------------------------------------------------------- transposes
__global__ void __launch_bounds__(256)
transpose_all(const float* __restrict__ Wv, const float* __restrict__ Wg,
              const float* __restrict__ Wmq, const float* __restrict__ Wmk,
              const float* __restrict__ Wq, const float* __restrict__ Wk,
              const float* __restrict__ Wo,
              float* __restrict__ WvT, float* __restrict__ WgT,
              float* __restrict__ WmqT, float* __restrict__ WmkT,
              float* __restrict__ WqT, float* __restrict__ WkT,
              float* __restrict__ WoT)
{
    __shared__ float t[32][33];
    const int z = blockIdx.x;
    const float* in; float* out; int R, C, tx, ty;
    if (z < 256)      { in = Wv;  out = WvT;  R = 512; C = 512;
                        tx = z & 15;          ty = z >> 4; }
    else if (z < 320) { in = Wg;  out = WgT;  R = 512; C = 128;
                        int l = z - 256; tx = l & 3;  ty = l >> 2; }
    else if (z < 384) { in = Wmq; out = WmqT; R = 128; C = 512;
                        int l = z - 320; tx = l & 15; ty = l >> 4; }
    else if (z < 448) { in = Wmk; out = WmkT; R = 128; C = 512;
                        int l = z - 384; tx = l & 15; ty = l >> 4; }
    else if (z < 704) { in = Wq;  out = WqT;  R = 512; C = 512;
                        int l = z - 448; tx = l & 15; ty = l >> 4; }
    else if (z < 960) { in = Wk;  out = WkT;  R = 512; C = 512;
                        int l = z - 704; tx = l & 15; ty = l >> 4; }
    else              { in = Wo;  out = WoT;  R = 512; C = 512;
                        int l = z - 960; tx = l & 15; ty = l >> 4; }

    const int c0 = tx * 32, r0 = ty * 32;
    const int x = threadIdx.x, y = threadIdx.y;
#pragma unroll
    for (int j = 0; j < 32; j += 8)
        t[y + j][x] = tf32f(in[(long long)(r0 + y + j) * C + c0 + x]);
    __syncthreads();
#pragma unroll
    for (int j = 0; j < 32; j += 8)
        out[(long long)(c0 + y + j) * R + r0 + x] = t[x][y + j];
}

__global__ void __launch_bounds__(256)
transpose_v(const float* __restrict__ v, float* __restrict__ vt)
{
    __shared__ float t[32][33];
    const int z = blockIdx.z, b = z >> 3, h = z & 7;
    const float* in = v + (long long)b * S_ * D_ + h * HD_;
    float* out = vt + (long long)z * HD_ * S_;
    const int s0 = blockIdx.x * 32, d0 = blockIdx.y * 32;
    const int x = threadIdx.x, y = threadIdx.y;
#pragma unroll
    for (int j = 0; j < 32; j += 8)
        t[y + j][x] = in[(long long)(s0 + y + j) * D_ + d0 + x];
    __syncthreads();
#pragma unroll
    for (int j = 0; j < 32; j += 8)
        out[(long long)(d0 + y + j) * S_ + s0 + x] = t[x][y + j];
}

// ---------------------------------------------------------------- launcher
extern "C" void kernel_launch(void* const* d_in, const int* in_sizes, int n_in,
                              void* d_out, int out_size)
{
    const float* query = (const float*)d_in[0];
    const float* key_  = (const float*)d_in[1];
    const float* value = (const float*)d_in[2];
    const float* Wq  = (const float*)d_in[3];
    const float* bq  = (const float*)d_in[4];
    const float* Wk  = (const float*)d_in[5];
    const float* bk  = (const float*)d_in[6];
    const float* Wv  = (const float*)d_in[7];
    const float* bv  = (const float*)d_in[8];
    const float* Wo  = (const float*)d_in[9];
    const float* bo  = (const float*)d_in[10];
    const float* Wg  = (const float*)d_in[11];
    const float* bg  = (const float*)d_in[12];
    const float* Wmq = (const float*)d_in[13];
    const float* bmq = (const float*)d_in[14];
    const float* Wmk = (const float*)d_in[15];
    const float* bmk = (const float*)d_in[16];

    float* out = (float*)d_out;                   // [B,S,D]
    float* P   = out + (long long)B_ * S_ * D_;   // [B,H,S,S]

    float *latent, *modq, *modk, *qb, *kb, *vb, *ao, *vt, *stats;
    float *WgT, *WmqT, *WmkT, *WqT, *WkT, *WvT, *WoT;
    cudaGetSymbolAddress((void**)&latent, g_latent);
    cudaGetSymbolAddress((void**)&modq, g_modq);
    cudaGetSymbolAddress((void**)&modk, g_modk);
    cudaGetSymbolAddress((void**)&qb, g_q);
    cudaGetSymbolAddress((void**)&kb, g_k);
    cudaGetSymbolAddress((void**)&vb, g_v);
    cudaGetSymbolAddress((void**)&ao, g_ao);
    cudaGetSymbolAddress((void**)&vt, g_vt);
    cudaGetSymbolAddress((void**)&stats, g_stats);
    cudaGetSymbolAddress((void**)&WgT, g_WgT);
    cudaGetSymbolAddress((void**)&WmqT, g_WmqT);
    cudaGetSymbolAddress((void**)&WmkT, g_WmkT);
    cudaGetSymbolAddress((void**)&WqT, g_WqT);
    cudaGetSymbolAddress((void**)&WkT, g_WkT);
    cudaGetSymbolAddress((void**)&WvT, g_WvT);
    cudaGetSymbolAddress((void**)&WoT, g_WoT);

    const int SMEMG   = 4 * 4096 * 4;                       // 64 KB
    const int SMEM_AT = (2 * 128 * 68 + 2 * 64 * 132 + 128 * 132 + 384) * 4;
    cudaFuncSetAttribute(tc_gemm<OP_RELU,    true>,
                         cudaFuncAttributeMaxDynamicSharedMemorySize, SMEMG);
    cudaFuncSetAttribute(tc_gemm<OP_SIGMOID, false>,
                         cudaFuncAttributeMaxDynamicSharedMemorySize, SMEMG);
    cudaFuncSetAttribute(tc_gemm<OP_MUL,     true>,
                         cudaFuncAttributeMaxDynamicSharedMemorySize, SMEMG);
    cudaFuncSetAttribute(tc_gemm<OP_NONE,    true>,
                         cudaFuncAttributeMaxDynamicSharedMemorySize, SMEMG);
    cudaFuncSetAttribute(tc_gemm<OP_NONE,    false>,
                         cudaFuncAttributeMaxDynamicSharedMemorySize, SMEMG);
    cudaFuncSetAttribute(attn_fused,
                         cudaFuncAttributeMaxDynamicSharedMemorySize, SMEM_AT);

    dim3 tb(32, 8);
    GemmJobs js;

    // idx 0: all weight transposes
    transpose_all<<<1216, tb>>>(Wv, Wg, Wmq, Wmk, Wq, Wk, Wo,
                                WvT, WgT, WmqT, WmkT, WqT, WkT, WoT);

    // idx 1: latent = relu(query @ Wg + bg)
    js.j[0] = { query, WgT, bg, nullptr, latent };
    js.j[1] = js.j[0];
    tc_gemm<OP_RELU, true><<<dim3(1, 64, 1), 128, SMEMG>>>(
        js, D_, D_, L_, BS_, L_, D_);

    // idx 2: dual modq/modk = sigmoid(latent @ Wm* + bm*)
    js.j[0] = { latent, WmqT, bmq, nullptr, modq };
    js.j[1] = { latent, WmkT, bmk, nullptr, modk };
    tc_gemm<OP_SIGMOID, false><<<dim3(4, 64, 2), 128, SMEMG>>>(
        js, L_, L_, D_, BS_, D_, L_);

    // idx 3 (profiled): dual q/k projections
    js.j[0] = { query, WqT, bq, modq, qb };
    js.j[1] = { key_,  WkT, bk, modk, kb };
    tc_gemm<OP_MUL, true><<<dim3(4, 64, 2), 128, SMEMG>>>(
        js, D_, D_, D_, BS_, D_, D_);

    // idx 4: v = value @ Wv + bv
    js.j[0] = { value, WvT, bv, nullptr, vb };
    js.j[1] = js.j[0];
    tc_gemm<OP_NONE, true><<<dim3(4, 64, 1), 128, SMEMG>>>(
        js, D_, D_, D_, BS_, D_, D_);

    // idx 5: vT per head
    transpose_v<<<dim3(S_ / 32, HD_ / 32, B_ * H_), tb>>>(vb, vt);

    // idx 6: fused attention, idx 7: normalize
    attn_fused<<<dim3(16, B_ * H_), 512, SMEM_AT>>>(qb, kb, vt, P, ao, stats);
    p_scale<<<dim3(B_ * H_ * S_), 256>>>(P, stats);

    // idx 8: output = attn_out @ Wo + bo
    js.j[0] = { ao, WoT, bo, nullptr, out };
    js.j[1] = js.j[0];
    tc_gemm<OP_NONE, false><<<dim3(4, 64, 1), 128, SMEMG>>>(
        js, D_, D_, D_, BS_, D_, D_);
}

// round 12
// speedup vs baseline: 1.0750x; 1.0750x over previous
#include <cuda_runtime.h>
#include <cstdint>

// ---------------------------------------------------------------- constants
#define B_   4
#define S_   2048
#define D_   512
#define H_   8
#define HD_  64
#define L_   128
#define BS_  (B_ * S_)

#define OP_NONE    0
#define OP_RELU    1
#define OP_SIGMOID 2
#define OP_MUL     3

// ---------------------------------------------------------------- scratch
__device__ float g_latent[BS_ * L_];
__device__ float g_modq[BS_ * D_];
__device__ float g_modk[BS_ * D_];
__device__ float g_q[BS_ * D_];
__device__ float g_k[BS_ * D_];
__device__ float g_v[BS_ * D_];
__device__ float g_ao[BS_ * D_];
__device__ float g_vt[B_ * H_ * HD_ * S_];      // [bh][hd][s]
__device__ float g_stats[B_ * H_ * S_];         // per attn row: 1/sum
__device__ float g_WgT[L_ * D_];
__device__ float g_WmqT[D_ * L_];
__device__ float g_WmkT[D_ * L_];
__device__ float g_WqT[D_ * D_];
__device__ float g_WkT[D_ * D_];
__device__ float g_WvT[D_ * D_];
__device__ float g_WoT[D_ * D_];

// ---------------------------------------------------------------- helpers
__device__ __forceinline__ uint32_t tf32r(float x) {
    float r;
    asm("cvt.rna.tf32.f32 %0, %1;" : "=f"(r) : "f"(x));
    return __float_as_uint(r);
}
__device__ __forceinline__ float tf32f(float x) {
    float r;
    asm("cvt.rna.tf32.f32 %0, %1;" : "=f"(r) : "f"(x));
    return r;
}
__device__ __forceinline__ uint32_t smem_u32(const void* p) {
    uint32_t a;
    asm("{ .reg .u64 t; cvta.to.shared.u64 t, %1; cvt.u32.u64 %0, t; }"
        : "=r"(a) : "l"(p));
    return a;
}
__device__ __forceinline__ void cp16(uint32_t saddr, const void* gaddr) {
    asm volatile("cp.async.cg.shared.global [%0], [%1], 16;"
                 :: "r"(saddr), "l"(gaddr));
}
#define CP_COMMIT() asm volatile("cp.async.commit_group;")
#define CP_WAIT1()  asm volatile("cp.async.wait_group 1;" ::: "memory")
#define CP_WAIT0()  asm volatile("cp.async.wait_group 0;" ::: "memory")

__device__ __forceinline__ void mma_tf32_16x8x8(
    float& c0, float& c1, float& c2, float& c3,
    uint32_t a0, uint32_t a1, uint32_t a2, uint32_t a3,
    uint32_t b0, uint32_t b1)
{
    asm volatile(
        "mma.sync.aligned.m16n8k8.row.col.f32.tf32.tf32.f32 "
        "{%0,%1,%2,%3}, {%4,%5,%6,%7}, {%8,%9}, {%0,%1,%2,%3};"
        : "+f"(c0), "+f"(c1), "+f"(c2), "+f"(c3)
        : "r"(a0), "r"(a1), "r"(a2), "r"(a3), "r"(b0), "r"(b1));
}

// ---------------------------------------------------------------- tc GEMM
// (R10 shape: 256 threads = 8 warps 2x4, BN=128, 2 CTAs/SM.)
struct GemmJob { const float *A, *Bm, *bias, *aux; float *C; };
struct GemmJobs { GemmJob j[2]; };

template<int BN, int OP, bool RND>
__global__ void __launch_bounds__(256, 2)
tc_gemm(GemmJobs jobs, int lda, int ldb, int ldc, int M, int N, int K)
{
    const GemmJob J = jobs.j[blockIdx.z];
    const float* __restrict__ A    = J.A;
    const float* __restrict__ Bm   = J.Bm;
    const float* __restrict__ bias = J.bias;
    const float* __restrict__ aux  = J.aux;
    float* __restrict__ C          = J.C;

    constexpr int NF  = BN / 32;
    constexpr int BLD = BN / 32;
    extern __shared__ float sm[];
    float* const A0 = sm;
    float* const A1 = A0 + 4096;
    float* const B0 = A1 + 4096;
    float* const B1 = B0 + BN * 32;

    const int tid  = threadIdx.x;
    const int wid  = tid >> 5;
    const int lane = tid & 31;
    const int wm   = wid >> 2;
    const int wn   = wid & 3;

    const int m0 = blockIdx.y * 128;
    const int n0 = blockIdx.x * BN;
    const int NC = K >> 5;

    float acc[4][NF][4];
#pragma unroll
    for (int i = 0; i < 4; i++)
#pragma unroll
        for (int j = 0; j < NF; j++)
#pragma unroll
            for (int r = 0; r < 4; r++) acc[i][j][r] = 0.f;

    float4 ar[4], br[BLD];

    auto loadA = [&](int kc) {
        const float* Ag = A + (long long)m0 * lda + kc * 32;
#pragma unroll
        for (int i = 0; i < 4; i++) {
            int idx = tid + i * 256;
            int m = idx >> 3, f4 = idx & 7;
            ar[i] = *(const float4*)(Ag + (long long)m * lda + f4 * 4);
        }
    };
    auto loadB = [&](int kc) {
        const float* Bg = Bm + (long long)n0 * ldb + kc * 32;
#pragma unroll
        for (int i = 0; i < BLD; i++) {
            int idx = tid + i * 256;
            int n = idx >> 3, f4 = idx & 7;
            br[i] = *(const float4*)(Bg + (long long)n * ldb + f4 * 4);
        }
    };
    auto stsA = [&](float* As) {
#pragma unroll
        for (int i = 0; i < 4; i++) {
            int idx = tid + i * 256;
            int m = idx >> 3, f4 = idx & 7;
            int fm = m >> 4, r = m & 15, ks = f4 >> 1, c4h = f4 & 1;
            int base = (fm * 4 + ks) * 128 + (r & 7) * 16 + (r >> 3) + (c4h << 1);
            uint32_t* Au = (uint32_t*)As;
            Au[base +  0] = tf32r(ar[i].x);
            Au[base +  4] = tf32r(ar[i].y);
            Au[base +  8] = tf32r(ar[i].z);
            Au[base + 12] = tf32r(ar[i].w);
        }
    };
    auto stsB = [&](float* Bs) {     // B pre-rounded: raw stores
#pragma unroll
        for (int i = 0; i < BLD; i++) {
            int idx = tid + i * 256;
            int n = idx >> 3, f4 = idx & 7;
            int fn = n >> 3, g = n & 7, ks = f4 >> 1, c4h = f4 & 1;
            int base = (fn * 4 + ks) * 64 + g * 8 + c4h;
            uint32_t* Bu = (uint32_t*)Bs;
            Bu[base + 0] = __float_as_uint(br[i].x);
            Bu[base + 2] = __float_as_uint(br[i].y);
            Bu[base + 4] = __float_as_uint(br[i].z);
            Bu[base + 6] = __float_as_uint(br[i].w);
        }
    };
    auto compute = [&](const float* As, const float* Bs) {
#pragma unroll
        for (int ks = 0; ks < 4; ks++) {
            uint32_t bf[NF][2];
#pragma unroll
            for (int fn = 0; fn < NF; fn++) {
                const float2 t = *(const float2*)
                    &Bs[(((wn * NF + fn) * 4 + ks) * 32 + lane) * 2];
                bf[fn][0] = __float_as_uint(t.x);
                bf[fn][1] = __float_as_uint(t.y);
            }
            uint32_t af[4][4];
#pragma unroll
            for (int fm = 0; fm < 4; fm++) {
                const float4 t = *(const float4*)
                    &As[(((wm * 4 + fm) * 4 + ks) * 32 + lane) * 4];
                af[fm][0] = __float_as_uint(t.x);
                af[fm][1] = __float_as_uint(t.y);
                af[fm][2] = __float_as_uint(t.z);
                af[fm][3] = __float_as_uint(t.w);
            }
#pragma unroll
            for (int fm = 0; fm < 4; fm++)
#pragma unroll
                for (int fn = 0; fn < NF; fn++)
                    mma_tf32_16x8x8(acc[fm][fn][0], acc[fm][fn][1],
                                    acc[fm][fn][2], acc[fm][fn][3],
                                    af[fm][0], af[fm][1], af[fm][2], af[fm][3],
                                    bf[fn][0], bf[fn][1]);
        }
    };

    loadA(0); loadB(0);
    stsA(A0); stsB(B0);
    __syncthreads();
    for (int kc = 0; kc < NC; kc++) {
        const int cur = kc & 1;
        if (kc + 1 < NC) { loadA(kc + 1); loadB(kc + 1); }
        compute(cur ? A1 : A0, cur ? B1 : B0);
        if (kc + 1 < NC) {
            stsA(cur ? A0 : A1);
            stsB(cur ? B0 : B1);
            __syncthreads();
        }
    }

    const int g = lane >> 2, t = lane & 3;
#pragma unroll
    for (int fm = 0; fm < 4; fm++) {
        const int row = m0 + wm * 64 + fm * 16 + g;
#pragma unroll
        for (int fn = 0; fn < NF; fn++) {
            const int col = n0 + wn * (BN / 4) + fn * 8 + t * 2;
#pragma unroll
            for (int half = 0; half < 2; half++) {
                const int rr = row + half * 8;
                float v0 = acc[fm][fn][half * 2 + 0];
                float v1 = acc[fm][fn][half * 2 + 1];
                if (bias) { v0 += bias[col]; v1 += bias[col + 1]; }
                if (OP == OP_RELU) {
                    v0 = fmaxf(v0, 0.f); v1 = fmaxf(v1, 0.f);
                } else if (OP == OP_SIGMOID) {
                    v0 = 1.f / (1.f + __expf(-v0));
                    v1 = 1.f / (1.f + __expf(-v1));
                } else if (OP == OP_MUL) {
                    const float2 m2 = *(const float2*)
                        &aux[(long long)rr * ldc + col];
                    v0 *= m2.x; v1 *= m2.y;
                }
                if (RND) { v0 = tf32f(v0); v1 = tf32f(v1); }
                float2 o; o.x = v0; o.y = v1;
                *(float2*)&C[(long long)rr * ldc + col] = o;
            }
        }
    }
}

// ---------------------------------------------------------------- fused attn
// (unchanged: streaming e -> P, row sums, O scaled.)
__global__ void __launch_bounds__(512, 1)
attn_fused(const float* __restrict__ qg, const float* __restrict__ kg,
           const float* __restrict__ vtg, float* __restrict__ P,
           float* __restrict__ ao, float* __restrict__ stats)
{
    extern __shared__ float sm[];
    float* const Ks0  = sm;                   // 128*68
    float* const Ks1  = Ks0 + 128 * 68;
    float* const Vs0  = Ks1 + 128 * 68;       // 64*132
    float* const Vs1  = Vs0 + 64 * 132;
    float* const Es   = Vs1 + 64 * 132;       // 128*132
    float* const ssum = Es + 128 * 132;       // 256
    float* const srv  = ssum + 256;           // 128

    const uint32_t sKs0 = smem_u32(Ks0);
    const uint32_t sKs1 = smem_u32(Ks1);
    const uint32_t sVs0 = smem_u32(Vs0);
    const uint32_t sVs1 = smem_u32(Vs1);

    const int tid  = threadIdx.x;
    const int wid  = tid >> 5;
    const int lane = tid & 31;
    const int wm   = wid >> 1;                // 0..7
    const int wn   = wid & 1;                 // 0..1
    const int g    = lane >> 2;
    const int t    = lane & 3;

    const int qt = blockIdx.x, z = blockIdx.y;
    const int b = z >> 3, h = z & 7;
    const long long offQK = (long long)b * S_ * D_ + (long long)h * HD_;
    const long long offP  = (long long)z * S_ * S_ + (long long)(qt * 128) * S_;
    const float* Vg = vtg + (long long)z * HD_ * S_;
    const float sc = 0.125f;

    const int kr = tid >> 4, kf = tid & 15;
    const int vd = tid >> 5, vf = tid & 31;
    auto issueK = [&](uint32_t sbase, int kt) {
        const float* Kg2 = kg + offQK + (long long)(kt * 128) * D_;
#pragma unroll
        for (int i = 0; i < 4; i++) {
            int r = kr + i * 32;
            cp16(sbase + (r * 68 + kf * 4) * 4, Kg2 + (long long)r * D_ + kf * 4);
        }
    };
    auto issueV = [&](uint32_t sbase, int kt) {
#pragma unroll
        for (int i = 0; i < 4; i++) {
            int d = vd + i * 16;
            cp16(sbase + (d * 132 + vf * 4) * 4,
                 Vg + (long long)d * S_ + kt * 128 + vf * 4);
        }
    };

    {
        const float* Qg = qg + offQK + (long long)(qt * 128) * D_;
#pragma unroll
        for (int i = 0; i < 4; i++) {
            int idx = tid + i * 512;
            int r = idx >> 4, f4 = idx & 15;
            float4 v = *(const float4*)(Qg + (long long)r * D_ + f4 * 4);
            *(float4*)&Es[r * 132 + f4 * 4] = v;
        }
    }
    issueK(sKs0, 0);
    issueV(sVs0, 0);
    CP_COMMIT();
    __syncthreads();

    uint32_t aq[8][4];
    {
        const int r0 = wm * 16 + g;
#pragma unroll
        for (int ks = 0; ks < 8; ks++) {
            aq[ks][0] = __float_as_uint(Es[r0 * 132 + ks * 8 + t]);
            aq[ks][1] = __float_as_uint(Es[(r0 + 8) * 132 + ks * 8 + t]);
            aq[ks][2] = __float_as_uint(Es[r0 * 132 + ks * 8 + t + 4]);
            aq[ks][3] = __float_as_uint(Es[(r0 + 8) * 132 + ks * 8 + t + 4]);
        }
    }

    float acco[4][4];
#pragma unroll
    for (int fn = 0; fn < 4; fn++)
#pragma unroll
        for (int r = 0; r < 4; r++) acco[fn][r] = 0.f;
    float rsum0 = 0.f, rsum1 = 0.f;

    for (int kt = 0; kt < 16; kt++) {
        const int cur = kt & 1;
        __syncthreads();
        if (kt < 15) {
            issueK(cur ? sKs0 : sKs1, kt + 1);
            issueV(cur ? sVs0 : sVs1, kt + 1);
            CP_COMMIT();
            CP_WAIT1();
        } else {
            CP_WAIT0();
        }
        __syncthreads();

        const float* Ksb = cur ? Ks1 : Ks0;
        const float* Vsb = cur ? Vs1 : Vs0;

        float accs[8][4];
#pragma unroll
        for (int fn = 0; fn < 8; fn++)
#pragma unroll
            for (int r = 0; r < 4; r++) accs[fn][r] = 0.f;
#pragma unroll
        for (int ks = 0; ks < 8; ks++) {
#pragma unroll
            for (int fn = 0; fn < 8; fn++) {
                const int n = wn * 64 + fn * 8 + g;
                uint32_t b0 = __float_as_uint(Ksb[n * 68 + ks * 8 + t]);
                uint32_t b1 = __float_as_uint(Ksb[n * 68 + ks * 8 + t + 4]);
                mma_tf32_16x8x8(accs[fn][0], accs[fn][1],
                                accs[fn][2], accs[fn][3],
                                aq[ks][0], aq[ks][1], aq[ks][2], aq[ks][3],
                                b0, b1);
            }
        }

        const int prow0 = wm * 16 + g;
#pragma unroll
        for (int fn = 0; fn < 8; fn++) {
            float2 eA, eB;
            eA.x = __expf(accs[fn][0] * sc);
            eA.y = __expf(accs[fn][1] * sc);
            eB.x = __expf(accs[fn][2] * sc);
            eB.y = __expf(accs[fn][3] * sc);
            rsum0 += eA.x + eA.y;
            rsum1 += eB.x + eB.y;
            const int col = wn * 64 + fn * 8 + t * 2;
            __stcs((float2*)&P[offP + (long long)prow0 * S_ + kt * 128 + col], eA);
            __stcs((float2*)&P[offP + (long long)(prow0 + 8) * S_ + kt * 128 + col], eB);
            float2 rA, rB;
            rA.x = tf32f(eA.x); rA.y = tf32f(eA.y);
            rB.x = tf32f(eB.x); rB.y = tf32f(eB.y);
            *(float2*)&Es[prow0 * 132 + col]       = rA;
            *(float2*)&Es[(prow0 + 8) * 132 + col] = rB;
        }

        asm volatile("bar.sync %0, 64;" :: "r"(1 + wm) : "memory");

#pragma unroll
        for (int ks = 0; ks < 16; ks++) {
            uint32_t a0 = __float_as_uint(Es[prow0 * 132 + ks * 8 + t]);
            uint32_t a1 = __float_as_uint(Es[(prow0 + 8) * 132 + ks * 8 + t]);
            uint32_t a2 = __float_as_uint(Es[prow0 * 132 + ks * 8 + t + 4]);
            uint32_t a3 = __float_as_uint(Es[(prow0 + 8) * 132 + ks * 8 + t + 4]);
#pragma unroll
            for (int fn = 0; fn < 4; fn++) {
                const int n = wn * 32 + fn * 8 + g;
                uint32_t b0 = __float_as_uint(Vsb[n * 132 + ks * 8 + t]);
                uint32_t b1 = __float_as_uint(Vsb[n * 132 + ks * 8 + t + 4]);
                mma_tf32_16x8x8(acco[fn][0], acco[fn][1],
                                acco[fn][2], acco[fn][3],
                                a0, a1, a2, a3, b0, b1);
            }
        }
    }

    rsum0 += __shfl_xor_sync(~0u, rsum0, 1);
    rsum0 += __shfl_xor_sync(~0u, rsum0, 2);
    rsum1 += __shfl_xor_sync(~0u, rsum1, 1);
    rsum1 += __shfl_xor_sync(~0u, rsum1, 2);
    __syncthreads();
    if (t == 0) {
        ssum[(wm * 16 + g) * 2 + wn]     = rsum0;
        ssum[(wm * 16 + g + 8) * 2 + wn] = rsum1;
    }
    __syncthreads();
    if (tid < 128) {
        float rv = 1.f / (ssum[tid * 2] + ssum[tid * 2 + 1]);
        srv[tid] = rv;
        stats[(long long)z * S_ + qt * 128 + tid] = rv;
    }
    __syncthreads();
    const float rv0 = srv[wm * 16 + g];
    const float rv1 = srv[wm * 16 + g + 8];

    const long long offC = (long long)b * S_ * D_ + (long long)h * HD_;
#pragma unroll
    for (int fn = 0; fn < 4; fn++) {
        const int col = wn * 32 + fn * 8 + t * 2;
        const int row = qt * 128 + wm * 16 + g;
        float2 oA, oB;
        oA.x = tf32f(acco[fn][0] * rv0); oA.y = tf32f(acco[fn][1] * rv0);
        oB.x = tf32f(acco[fn][2] * rv1); oB.y = tf32f(acco[fn][3] * rv1);
        *(float2*)&ao[offC + (long long)row * D_ + col] = oA;
        *(float2*)&ao[offC + (long long)(row + 8) * D_ + col] = oB;
    }
}

// ---------------------------------------------------------------- P scale
__global__ void __launch_bounds__(256)
p_scale(float* __restrict__ P, const float* __restrict__ stats)
{
    const long long row = blockIdx.x;
    float* p = P + row * S_;
    const float rv = stats[row];
    const int tid = threadIdx.x;
    float4 v0 = __ldcs((const float4*)(p + tid * 4));
    float4 v1 = __ldcs((const float4*)(p + (tid + 256) * 4));
    v0.x *= rv; v0.y *= rv; v0.z *= rv; v0.w *= rv;
    v1.x *= rv; v1.y *= rv; v1.z *= rv; v1.w *= rv;
    __stcs((float4*)(p + tid * 4), v0);
    __stcs((float4*)(p + (tid + 256) * 4), v1);
}

// ---------------------------------------------------------------- transposes
__global__ void __launch_bounds__(256)
transpose_all(const float* __restrict__ Wv, const float* __restrict__ Wg,
              const float* __restrict__ Wmq, const float* __restrict__ Wmk,
              const float* __restrict__ Wq, const float* __restrict__ Wk,
              const float* __restrict__ Wo,
              float* __restrict__ WvT, float* __restrict__ WgT,
              float* __restrict__ WmqT, float* __restrict__ WmkT,
              float* __restrict__ WqT, float* __restrict__ WkT,
              float* __restrict__ WoT)
{
    __shared__ float t[32][33];
    const int z = blockIdx.x;
    const float* in; float* out; int R, C, tx, ty;
    if (z < 256)      { in = Wv;  out = WvT;  R = 512; C = 512;
                        tx = z & 15;          ty = z >> 4; }
    else if (z < 320) { in = Wg;  out = WgT;  R = 512; C = 128;
                        int l = z - 256; tx = l & 3;  ty = l >> 2; }
    else if (z < 384) { in = Wmq; out = WmqT; R = 128; C = 512;
                        int l = z - 320; tx = l & 15; ty = l >> 4; }
    else if (z < 448) { in = Wmk; out = WmkT; R = 128; C = 512;
                        int l = z - 384; tx = l & 15; ty = l >> 4; }
    else if (z < 704) { in = Wq;  out = WqT;  R = 512; C = 512;
                        int l = z - 448; tx = l & 15; ty = l >> 4; }
    else if (z < 960) { in = Wk;  out = WkT;  R = 512; C = 512;
                        int l = z - 704; tx = l & 15; ty = l >> 4; }
    else              { in = Wo;  out = WoT;  R = 512; C = 512;
                        int l = z - 960; tx = l & 15; ty = l >> 4; }

    const int c0 = tx * 32, r0 = ty * 32;
    const int x = threadIdx.x, y = threadIdx.y;
#pragma unroll
    for (int j = 0; j < 32; j += 8)
        t[y + j][x] = tf32f(in[(long long)(r0 + y + j) * C + c0 + x]);
    __syncthreads();
#pragma unroll
    for (int j = 0; j < 32; j += 8)
        out[(long long)(c0 + y + j) * R + r0 + x] = t[x][y + j];
}

__global__ void __launch_bounds__(256)
transpose_v(const float* __restrict__ v, float* __restrict__ vt)
{
    __shared__ float t[32][33];
    const int z = blockIdx.z, b = z >> 3, h = z & 7;
    const float* in = v + (long long)b * S_ * D_ + h * HD_;
    float* out = vt + (long long)z * HD_ * S_;
    const int s0 = blockIdx.x * 32, d0 = blockIdx.y * 32;
    const int x = threadIdx.x, y = threadIdx.y;
#pragma unroll
    for (int j = 0; j < 32; j += 8)
        t[y + j][x] = in[(long long)(s0 + y + j) * D_ + d0 + x];
    __syncthreads();
#pragma unroll
    for (int j = 0; j < 32; j += 8)
        out[(long long)(d0 + y + j) * S_ + s0 + x] = t[x][y + j];
}

// ---------------------------------------------------------------- launcher
extern "C" void kernel_launch(void* const* d_in, const int* in_sizes, int n_in,
                              void* d_out, int out_size)
{
    const float* query = (const float*)d_in[0];
    const float* key_  = (const float*)d_in[1];
    const float* value = (const float*)d_in[2];
    const float* Wq  = (const float*)d_in[3];
    const float* bq  = (const float*)d_in[4];
    const float* Wk  = (const float*)d_in[5];
    const float* bk  = (const float*)d_in[6];
    const float* Wv  = (const float*)d_in[7];
    const float* bv  = (const float*)d_in[8];
    const float* Wo  = (const float*)d_in[9];
    const float* bo  = (const float*)d_in[10];
    const float* Wg  = (const float*)d_in[11];
    const float* bg  = (const float*)d_in[12];
    const float* Wmq = (const float*)d_in[13];
    const float* bmq = (const float*)d_in[14];
    const float* Wmk = (const float*)d_in[15];
    const float* bmk = (const float*)d_in[16];

    float* out = (float*)d_out;                   // [B,S,D]
    float* P   = out + (long long)B_ * S_ * D_;   // [B,H,S,S]

    float *latent, *modq, *modk, *qb, *kb, *vb, *ao, *vt, *stats;
    float *WgT, *WmqT, *WmkT, *WqT, *WkT, *WvT, *WoT;
    cudaGetSymbolAddress((void**)&latent, g_latent);
    cudaGetSymbolAddress((void**)&modq, g_modq);
    cudaGetSymbolAddress((void**)&modk, g_modk);
    cudaGetSymbolAddress((void**)&qb, g_q);
    cudaGetSymbolAddress((void**)&kb, g_k);
    cudaGetSymbolAddress((void**)&vb, g_v);
    cudaGetSymbolAddress((void**)&ao, g_ao);
    cudaGetSymbolAddress((void**)&vt, g_vt);
    cudaGetSymbolAddress((void**)&stats, g_stats);
    cudaGetSymbolAddress((void**)&WgT, g_WgT);
    cudaGetSymbolAddress((void**)&WmqT, g_WmqT);
    cudaGetSymbolAddress((void**)&WmkT, g_WmkT);
    cudaGetSymbolAddress((void**)&WqT, g_WqT);
    cudaGetSymbolAddress((void**)&WkT, g_WkT);
    cudaGetSymbolAddress((void**)&WvT, g_WvT);
    cudaGetSymbolAddress((void**)&WoT, g_WoT);

    const int SMEM128 = (4096 * 2 + 128 * 32 * 2) * 4;     // 64 KB
    const int SMEM_AT = (2 * 128 * 68 + 2 * 64 * 132 + 128 * 132 + 384) * 4;
    cudaFuncSetAttribute(tc_gemm<128, OP_RELU,    true>,
                         cudaFuncAttributeMaxDynamicSharedMemorySize, SMEM128);
    cudaFuncSetAttribute(tc_gemm<128, OP_SIGMOID, false>,
                         cudaFuncAttributeMaxDynamicSharedMemorySize, SMEM128);
    cudaFuncSetAttribute(tc_gemm<128, OP_MUL,     true>,
                         cudaFuncAttributeMaxDynamicSharedMemorySize, SMEM128);
    cudaFuncSetAttribute(tc_gemm<128, OP_NONE,    true>,
                         cudaFuncAttributeMaxDynamicSharedMemorySize, SMEM128);
    cudaFuncSetAttribute(tc_gemm<128, OP_NONE,    false>,
                         cudaFuncAttributeMaxDynamicSharedMemorySize, SMEM128);
    cudaFuncSetAttribute(attn_fused,
                         cudaFuncAttributeMaxDynamicSharedMemorySize, SMEM_AT);

    // side stream + events (host objects only; created per call, not freed —
    // kernel_launch runs only a handful of times outside the timed replay)
    cudaStream_t s2;
    cudaStreamCreateWithFlags(&s2, cudaStreamNonBlocking);
    cudaEvent_t evFork, evV, evA, evP;
    cudaEventCreateWithFlags(&evFork, cudaEventDisableTiming);
    cudaEventCreateWithFlags(&evV,    cudaEventDisableTiming);
    cudaEventCreateWithFlags(&evA,    cudaEventDisableTiming);
    cudaEventCreateWithFlags(&evP,    cudaEventDisableTiming);

    dim3 tb(32, 8);
    GemmJobs js;

    // idx 0: all weight transposes (main stream)
    transpose_all<<<1216, tb>>>(Wv, Wg, Wmq, Wmk, Wq, Wk, Wo,
                                WvT, WgT, WmqT, WmkT, WqT, WkT, WoT);
    cudaEventRecord(evFork, 0);

    // main chain: latent -> mod -> q/k
    // idx 1: latent = relu(query @ Wg + bg)
    js.j[0] = { query, WgT, bg, nullptr, latent };
    js.j[1] = js.j[0];
    tc_gemm<128, OP_RELU, true><<<dim3(1, 64, 1), 256, SMEM128>>>(
        js, D_, D_, L_, BS_, L_, D_);
    // idx 2: dual modq/modk
    js.j[0] = { latent, WmqT, bmq, nullptr, modq };
    js.j[1] = { latent, WmkT, bmk, nullptr, modk };
    tc_gemm<128, OP_SIGMOID, false><<<dim3(4, 64, 2), 256, SMEM128>>>(
        js, L_, L_, D_, BS_, D_, L_);
    // idx 3 (profiled): dual q/k projections
    js.j[0] = { query, WqT, bq, modq, qb };
    js.j[1] = { key_,  WkT, bk, modk, kb };
    tc_gemm<128, OP_MUL, true><<<dim3(4, 64, 2), 256, SMEM128>>>(
        js, D_, D_, D_, BS_, D_, D_);

    // forked V chain on s2 (independent of latent/mod/qk)
    cudaStreamWaitEvent(s2, evFork, 0);
    js.j[0] = { value, WvT, bv, nullptr, vb };
    js.j[1] = js.j[0];
    tc_gemm<128, OP_NONE, true><<<dim3(4, 64, 1), 256, SMEM128, s2>>>(
        js, D_, D_, D_, BS_, D_, D_);
    transpose_v<<<dim3(S_ / 32, HD_ / 32, B_ * H_), tb, 0, s2>>>(vb, vt);
    cudaEventRecord(evV, s2);

    // join V chain, run fused attention on main stream
    cudaStreamWaitEvent(0, evV, 0);
    attn_fused<<<dim3(16, B_ * H_), 512, SMEM_AT>>>(qb, kb, vt, P, ao, stats);
    cudaEventRecord(evA, 0);

    // p_scale (DRAM-bound) on s2, concurrent with final GEMM (tensor-bound)
    cudaStreamWaitEvent(s2, evA, 0);
    p_scale<<<dim3(B_ * H_ * S_), 256, 0, s2>>>(P, stats);
    cudaEventRecord(evP, s2);

    // final GEMM on main stream
    js.j[0] = { ao, WoT, bo, nullptr, out };
    js.j[1] = js.j[0];
    tc_gemm<128, OP_NONE, false><<<dim3(4, 64, 1), 256, SMEM128>>>(
        js, D_, D_, D_, BS_, D_, D_);

    // join p_scale branch back into main stream
    cudaStreamWaitEvent(0, evP, 0);
}